// round 15
// baseline (speedup 1.0000x reference)
#include <cuda_runtime.h>
#include <cstdint>

#define Bn   16
#define ND   8192
#define NE   16384
#define NEDGE 65536
#define H    128
#define CAP  64
#define PGRID 296   // 2 CTAs x 148 SMs

typedef unsigned long long u64;
typedef unsigned int u32;

// ---------------- scratch ----------------
__device__ float g_Y[(size_t)Bn * ND * H];
__device__ float g_aggPre[(size_t)Bn * ND * H];
__device__ float g_Wt[4 * H * H];                // transposed weights [k][c]

__device__ int g_cntE[NE];
__device__ int g_lstE[NE * CAP];
__device__ int g_cntD[ND];
__device__ int g_lstD[ND * CAP];

// ---------------- cp.async helpers ----------------
__device__ __forceinline__ u32 cvta_s(const void* p) {
    u32 a;
    asm("{ .reg .u64 t; cvta.to.shared.u64 t, %1; cvt.u32.u64 %0, t; }" : "=r"(a) : "l"(p));
    return a;
}
#define CPA16(s, g)   asm volatile("cp.async.cg.shared.global [%0], [%1], 16;" :: "r"(s), "l"(g) : "memory")
#define CPA_COMMIT()  asm volatile("cp.async.commit_group;" ::: "memory")
#define CPA_WAIT(n)   asm volatile("cp.async.wait_group %0;" :: "n"(n) : "memory")

// 64x128 floats = 2048 float4, 256 thr -> 8 each
__device__ __forceinline__ void cpa_tile(u32 sdst, const float* __restrict__ g, int t) {
#pragma unroll
    for (int i = 0; i < 8; i++)
        CPA16(sdst + (u32)(t + 256 * i) * 16u, g + (size_t)(t + 256 * i) * 4);
}
// 128x128 floats = 4096 float4 -> 16 each
__device__ __forceinline__ void cpa_w(u32 sdst, const float* __restrict__ g, int t) {
#pragma unroll
    for (int i = 0; i < 16; i++)
        CPA16(sdst + (u32)(t + 256 * i) * 16u, g + (size_t)(t + 256 * i) * 4);
}

// ---------------- setup ----------------
__global__ void k_prep(const float* __restrict__ W0, const float* __restrict__ W1,
                       const float* __restrict__ W2, const float* __restrict__ W3,
                       float* __restrict__ Wt) {
    int g = blockIdx.x * 256 + threadIdx.x;
    int m = g >> 14;
    int idx = g & 16383;
    int k = idx >> 7, c = idx & 127;
    const float* W = (m == 0) ? W0 : (m == 1) ? W1 : (m == 2) ? W2 : W3;
    Wt[g] = W[c * H + k];
    if (g < NE) g_cntE[g] = 0;
    if (g < ND) g_cntD[g] = 0;
}

__global__ void k_fill(const int* __restrict__ e_d2e, const int* __restrict__ e_e2d) {
    int e = blockIdx.x * blockDim.x + threadIdx.x;
    if (e >= NEDGE) return;
    {
        int d = e_d2e[NEDGE + e];
        int p = atomicAdd(&g_cntE[d], 1);
        if (p < CAP) g_lstE[d * CAP + p] = e_d2e[e];
    }
    {
        int d = e_e2d[NEDGE + e];
        int p = atomicAdd(&g_cntD[d], 1);
        if (p < CAP) g_lstD[d * CAP + p] = e_e2d[e];
    }
}

// ---------------- mean-gather: warp per (node, batch) ----------------
__global__ void k_agg(const float* __restrict__ SRC, const int* __restrict__ cnt,
                      const int* __restrict__ lst, float* __restrict__ agg,
                      int nNodes, long srcStride) {
    int gw = (blockIdx.x * blockDim.x + threadIdx.x) >> 5;
    if (gw >= nNodes * Bn) return;
    int node = gw % nNodes;
    int b    = gw / nNodes;
    int lane = threadIdx.x & 31;

    int deg = cnt[node];
    int n = deg < CAP ? deg : CAP;
    const int* l = lst + node * CAP;
    float4 a = make_float4(0.f, 0.f, 0.f, 0.f);
    const float* base = SRC + (size_t)b * srcStride;
    for (int j = 0; j < n; ++j) {
        int src = l[j];
        float4 v = reinterpret_cast<const float4*>(base + (size_t)src * H)[lane];
        a.x += v.x; a.y += v.y; a.z += v.z; a.w += v.w;
    }
    float sc = 1.0f / fmaxf((float)deg, 1.0f);
    a.x *= sc; a.y *= sc; a.z *= sc; a.w *= sc;
    reinterpret_cast<float4*>(agg + ((size_t)b * nNodes + node) * H)[lane] = a;
}

// ---------------- GEMM inner: 64-k chunk over [kb, kb+64) ----------------
__device__ __forceinline__ void mm_chunk(const float* __restrict__ Xs,
                                         const float* __restrict__ Wc,
                                         int tr, int tc, int kb, u64 acc[4][4]) {
    const float* xb = Xs + tr * 4 * 128 + kb;
    const float* wb = Wc + 2 * tc;
#pragma unroll 2
    for (int k0 = 0; k0 < 64; k0 += 4) {
        float4 xq[4];
#pragma unroll
        for (int i = 0; i < 4; i++)
            xq[i] = *reinterpret_cast<const float4*>(xb + i * 128 + k0);
#pragma unroll
        for (int kk = 0; kk < 4; kk++) {
            u64 wv[4];
#pragma unroll
            for (int j = 0; j < 4; j++)
                wv[j] = *reinterpret_cast<const u64*>(wb + (k0 + kk) * 128 + 32 * j);
#pragma unroll
            for (int i = 0; i < 4; i++) {
                float xs = (kk == 0) ? xq[i].x : (kk == 1) ? xq[i].y
                         : (kk == 2) ? xq[i].z : xq[i].w;
                u64 xd;
                asm("mov.b64 %0, {%1, %1};" : "=l"(xd) : "f"(xs));
#pragma unroll
                for (int j = 0; j < 4; j++)
                    asm("fma.rn.f32x2 %0, %1, %2, %0;"
                        : "+l"(acc[i][j]) : "l"(wv[j]), "l"(xd));
            }
        }
    }
}

#define PSMEM ((128 * 128 + 64 * 128) * 4)        // W resident + X tile = 96 KB
#define DSMEM ((64 * 128 * 3) * 4)                // gemmD: X + 2 W chunks = 96 KB

// ---------------- persistent MODE 0: Y = X @ Wt ----------------
__global__ void __launch_bounds__(256, 2)
k_gemm0(const float* __restrict__ X, const float* __restrict__ Wt,
        float* __restrict__ out, int nTiles) {
    extern __shared__ float smx[];
    float* Ws = smx;                 // 128x128 resident
    float* Xs = smx + 128 * 128;     // 64x128
    const int t = threadIdx.x;
    const u32 sW = cvta_s(Ws), sX = cvta_s(Xs);

    cpa_w(sW, Wt, t);
    cpa_tile(sX, X + (size_t)blockIdx.x * 64 * H, t);
    CPA_COMMIT();

    const int tc = t & 15, tr = t >> 4;
    for (int tile = blockIdx.x; tile < nTiles; tile += PGRID) {
        CPA_WAIT(0);
        __syncthreads();

        u64 acc[4][4];
#pragma unroll
        for (int i = 0; i < 4; i++)
#pragma unroll
            for (int j = 0; j < 4; j++) acc[i][j] = 0ull;
        mm_chunk(Xs, Ws, tr, tc, 0, acc);
        mm_chunk(Xs, Ws + 64 * 128, tr, tc, 64, acc);

        __syncthreads();                     // everyone done with Xs
        int next = tile + PGRID;
        if (next < nTiles) {
            cpa_tile(sX, X + (size_t)next * 64 * H, t);
            CPA_COMMIT();
        }

        const size_t row0 = (size_t)tile * 64;
#pragma unroll
        for (int i = 0; i < 4; i++) {
            float* orow = out + (row0 + tr * 4 + i) * H + 2 * tc;
#pragma unroll
            for (int j = 0; j < 4; j++)
                *reinterpret_cast<u64*>(orow + 32 * j) = acc[i][j];
        }
    }
}

// ---------------- persistent Phase-1 E-side: GEMM + fused gather + LN --------
__global__ void __launch_bounds__(256, 2)
k_gemmE(const float* __restrict__ X, const float* __restrict__ Wt,
        const float* __restrict__ Y,
        const int* __restrict__ cnt, const int* __restrict__ lst,
        const float* __restrict__ ew,
        const float* __restrict__ bias, const float* __restrict__ gamma,
        const float* __restrict__ beta, float* __restrict__ out, int nTiles) {
    extern __shared__ float smx[];
    float* Ws = smx;
    float* Xs = smx + 128 * 128;
    const int t = threadIdx.x;
    const u32 sW = cvta_s(Ws), sX = cvta_s(Xs);

    cpa_w(sW, Wt, t);
    cpa_tile(sX, X + (size_t)blockIdx.x * 64 * H, t);
    CPA_COMMIT();

    const int tc = t & 15, tr = t >> 4;
    float2 b2[4], g2[4], be2[4];
#pragma unroll
    for (int j = 0; j < 4; j++) {
        b2[j]  = *reinterpret_cast<const float2*>(bias  + 2 * tc + 32 * j);
        g2[j]  = *reinterpret_cast<const float2*>(gamma + 2 * tc + 32 * j);
        be2[j] = *reinterpret_cast<const float2*>(beta  + 2 * tc + 32 * j);
    }

    for (int tile = blockIdx.x; tile < nTiles; tile += PGRID) {
        CPA_WAIT(0);
        __syncthreads();

        u64 acc[4][4];
#pragma unroll
        for (int i = 0; i < 4; i++)
#pragma unroll
            for (int j = 0; j < 4; j++) acc[i][j] = 0ull;
        mm_chunk(Xs, Ws, tr, tc, 0, acc);
        mm_chunk(Xs, Ws + 64 * 128, tr, tc, 64, acc);

        __syncthreads();
        int next = tile + PGRID;
        if (next < nTiles) {
            cpa_tile(sX, X + (size_t)next * 64 * H, t);
            CPA_COMMIT();
        }

        const size_t row0 = (size_t)tile * 64;
        const int b = (int)(row0 / NE);
        const int e0 = (int)(row0 % NE);
        const float* Yb = Y + (size_t)b * ND * H + 2 * tc;

#pragma unroll
        for (int i = 0; i < 4; i++) {
            const int e = e0 + tr * 4 + i;
            const size_t r = row0 + tr * 4 + i;
            int deg = cnt[e];
            int n = deg < CAP ? deg : CAP;
            const int* l = lst + e * CAP;
            float sc = (1.0f / (1.0f + __expf(-ew[e]))) / fmaxf((float)deg, 1.0f);

            float2 ag[4];
#pragma unroll
            for (int j = 0; j < 4; j++) ag[j] = make_float2(0.f, 0.f);
            for (int p = 0; p < n; ++p) {
                const float* yr = Yb + (size_t)l[p] * H;
#pragma unroll
                for (int j = 0; j < 4; j++) {
                    float2 v = *reinterpret_cast<const float2*>(yr + 32 * j);
                    ag[j].x += v.x; ag[j].y += v.y;
                }
            }

            float tv[8];
            float ssum = 0.f, q = 0.f;
            const float* xrow = X + r * H + 2 * tc;    // L2-hot residual
#pragma unroll
            for (int j = 0; j < 4; j++) {
                float plo, phi;
                asm("mov.b64 {%0, %1}, %2;" : "=f"(plo), "=f"(phi) : "l"(acc[i][j]));
                float2 x2 = *reinterpret_cast<const float2*>(xrow + 32 * j);
                float t0 = plo + ag[j].x * sc + b2[j].x; t0 = fmaxf(t0, 0.f); t0 += x2.x;
                float t1 = phi + ag[j].y * sc + b2[j].y; t1 = fmaxf(t1, 0.f); t1 += x2.y;
                tv[2 * j] = t0; tv[2 * j + 1] = t1;
                ssum += t0 + t1;
                q += t0 * t0 + t1 * t1;
            }
#pragma unroll
            for (int o = 8; o; o >>= 1) {
                ssum += __shfl_xor_sync(0xffffffffu, ssum, o, 16);
                q    += __shfl_xor_sync(0xffffffffu, q, o, 16);
            }
            float m = ssum * (1.0f / 128.0f);
            float rstd = rsqrtf(q * (1.0f / 128.0f) - m * m + 1e-5f);
            float* orow = out + r * H + 2 * tc;
#pragma unroll
            for (int j = 0; j < 4; j++) {
                float2 o2;
                o2.x = (tv[2 * j]     - m) * rstd * g2[j].x + be2[j].x;
                o2.y = (tv[2 * j + 1] - m) * rstd * g2[j].y + be2[j].y;
                *reinterpret_cast<float2*>(orow + 32 * j) = o2;
            }
        }
    }
}

// ---------------- Phase-2 D-side dual GEMM + LN (R13 structure) ----------------
__global__ void __launch_bounds__(256, 2)
k_gemmD(const float* __restrict__ X, const float* __restrict__ W1t,
        const float* __restrict__ A, const float* __restrict__ W2t,
        const float* __restrict__ bias, const float* __restrict__ gamma,
        const float* __restrict__ beta, float* __restrict__ out) {
    extern __shared__ float smx[];
    float* Xs = smx;
    float* Wc0 = smx + 64 * 128;
    float* Wc1 = smx + 2 * 64 * 128;
    const int t = threadIdx.x;
    const size_t row0 = (size_t)blockIdx.x * 64;

    const u32 sX = cvta_s(Xs), sW0 = cvta_s(Wc0), sW1 = cvta_s(Wc1);
    cpa_tile(sX, X + row0 * H, t);
    cpa_tile(sW0, W1t, t);
    CPA_COMMIT();
    cpa_tile(sW1, W1t + 64 * 128, t);
    CPA_COMMIT();

    const int tc = t & 15, tr = t >> 4;
    u64 acc[4][4];
#pragma unroll
    for (int i = 0; i < 4; i++)
#pragma unroll
        for (int j = 0; j < 4; j++) acc[i][j] = 0ull;

    CPA_WAIT(1);
    __syncthreads();
    mm_chunk(Xs, Wc0, tr, tc, 0, acc);
    CPA_WAIT(0);
    __syncthreads();
    cpa_tile(sW0, W2t, t);
    CPA_COMMIT();
    mm_chunk(Xs, Wc1, tr, tc, 64, acc);
    __syncthreads();
    cpa_tile(sX, A + row0 * H, t);
    cpa_tile(sW1, W2t + 64 * 128, t);
    CPA_COMMIT();
    CPA_WAIT(0);
    __syncthreads();
    mm_chunk(Xs, Wc0, tr, tc, 0, acc);
    mm_chunk(Xs, Wc1, tr, tc, 64, acc);

    float2 b2[4], g2[4], be2[4];
#pragma unroll
    for (int j = 0; j < 4; j++) {
        b2[j]  = *reinterpret_cast<const float2*>(bias  + 2 * tc + 32 * j);
        g2[j]  = *reinterpret_cast<const float2*>(gamma + 2 * tc + 32 * j);
        be2[j] = *reinterpret_cast<const float2*>(beta  + 2 * tc + 32 * j);
    }
#pragma unroll
    for (int i = 0; i < 4; i++) {
        const size_t r = row0 + tr * 4 + i;
        float tv[8];
        float ssum = 0.f, q = 0.f;
        const float* xrow = X + r * H + 2 * tc;
#pragma unroll
        for (int j = 0; j < 4; j++) {
            float plo, phi;
            asm("mov.b64 {%0, %1}, %2;" : "=f"(plo), "=f"(phi) : "l"(acc[i][j]));
            float2 x2 = *reinterpret_cast<const float2*>(xrow + 32 * j);
            float t0 = plo + b2[j].x; t0 = fmaxf(t0, 0.f); t0 += x2.x;
            float t1 = phi + b2[j].y; t1 = fmaxf(t1, 0.f); t1 += x2.y;
            tv[2 * j] = t0; tv[2 * j + 1] = t1;
            ssum += t0 + t1;
            q += t0 * t0 + t1 * t1;
        }
#pragma unroll
        for (int o = 8; o; o >>= 1) {
            ssum += __shfl_xor_sync(0xffffffffu, ssum, o, 16);
            q    += __shfl_xor_sync(0xffffffffu, q, o, 16);
        }
        float m = ssum * (1.0f / 128.0f);
        float rstd = rsqrtf(q * (1.0f / 128.0f) - m * m + 1e-5f);
        float* orow = out + r * H + 2 * tc;
#pragma unroll
        for (int j = 0; j < 4; j++) {
            float2 o2;
            o2.x = (tv[2 * j]     - m) * rstd * g2[j].x + be2[j].x;
            o2.y = (tv[2 * j + 1] - m) * rstd * g2[j].y + be2[j].y;
            *reinterpret_cast<float2*>(orow + 32 * j) = o2;
        }
    }
}

// ---------------- launch ----------------
extern "C" void kernel_launch(void* const* d_in, const int* in_sizes, int n_in,
                              void* d_out, int out_size) {
    const float* hD    = (const float*)d_in[0];
    const float* hE    = (const float*)d_in[1];
    const int*   e_d2e = (const int*)d_in[2];
    const int*   e_e2d = (const int*)d_in[3];
    const float* ew    = (const float*)d_in[4];
    const float* W_d2e    = (const float*)d_in[5];
    const float* W_e_self = (const float*)d_in[6];
    const float* b_e   = (const float*)d_in[7];
    const float* g_e   = (const float*)d_in[8];
    const float* be_e  = (const float*)d_in[9];
    const float* W_e2d    = (const float*)d_in[10];
    const float* W_d_self = (const float*)d_in[11];
    const float* b_d   = (const float*)d_in[12];
    const float* g_d   = (const float*)d_in[13];
    const float* be_d  = (const float*)d_in[14];

    float* out_hD = (float*)d_out;
    float* out_hE = (float*)d_out + (size_t)Bn * ND * H;

    float *pY, *pAggPre, *pWt;
    int *pCntE, *pLstE, *pCntD, *pLstD;
    cudaGetSymbolAddress((void**)&pY, g_Y);
    cudaGetSymbolAddress((void**)&pAggPre, g_aggPre);
    cudaGetSymbolAddress((void**)&pWt, g_Wt);
    cudaGetSymbolAddress((void**)&pCntE, g_cntE);
    cudaGetSymbolAddress((void**)&pLstE, g_lstE);
    cudaGetSymbolAddress((void**)&pCntD, g_cntD);
    cudaGetSymbolAddress((void**)&pLstD, g_lstD);

    float* Wt_d2e    = pWt + 0 * H * H;
    float* Wt_e_self = pWt + 1 * H * H;
    float* Wt_e2d    = pWt + 2 * H * H;
    float* Wt_d_self = pWt + 3 * H * H;

    cudaFuncSetAttribute(k_gemm0, cudaFuncAttributeMaxDynamicSharedMemorySize, PSMEM);
    cudaFuncSetAttribute(k_gemmE, cudaFuncAttributeMaxDynamicSharedMemorySize, PSMEM);
    cudaFuncSetAttribute(k_gemmD, cudaFuncAttributeMaxDynamicSharedMemorySize, DSMEM);

    // ---- setup ----
    k_prep<<<256, 256>>>(W_d2e, W_e_self, W_e2d, W_d_self, pWt);
    k_fill<<<NEDGE / 256, 256>>>(e_d2e, e_e2d);

    // ---- Phase 1: D -> E ----
    k_gemm0<<<PGRID, 256, PSMEM>>>(hD, Wt_d2e, pY, (Bn * ND) / 64);
    k_gemmE<<<PGRID, 256, PSMEM>>>(hE, Wt_e_self, pY, pCntE, pLstE, ew,
                                   b_e, g_e, be_e, out_hE, (Bn * NE) / 64);

    // ---- Phase 2: E -> D (commuted aggregation + dual GEMM) ----
    k_agg<<<(ND * Bn * 32) / 256, 256>>>(out_hE, pCntD, pLstD, pAggPre, ND, (long)NE * H);
    k_gemmD<<<(Bn * ND) / 64, 256, DSMEM>>>(hD, Wt_d_self, pAggPre, Wt_e2d,
                                            b_d, g_d, be_d, out_hD);
}

// round 16
// speedup vs baseline: 1.0673x; 1.0673x over previous
#include <cuda_runtime.h>
#include <cstdint>

#define Bn   16
#define ND   8192
#define NE   16384
#define NEDGE 65536
#define H    128
#define CAP  64

typedef unsigned long long u64;
typedef unsigned int u32;

// ---------------- scratch ----------------
__device__ float g_Y[(size_t)Bn * ND * H];
__device__ float g_aggPre[(size_t)Bn * ND * H];
__device__ float g_Wt[4 * H * H];                // transposed weights [k][c]

__device__ int g_cntE[NE];
__device__ int g_lstE[NE * CAP];
__device__ int g_cntD[ND];
__device__ int g_lstD[ND * CAP];

// ---------------- cp.async helpers ----------------
__device__ __forceinline__ u32 cvta_s(const void* p) {
    u32 a;
    asm("{ .reg .u64 t; cvta.to.shared.u64 t, %1; cvt.u32.u64 %0, t; }" : "=r"(a) : "l"(p));
    return a;
}
#define CPA16(s, g)   asm volatile("cp.async.cg.shared.global [%0], [%1], 16;" :: "r"(s), "l"(g) : "memory")
#define CPA_COMMIT()  asm volatile("cp.async.commit_group;" ::: "memory")
#define CPA_WAIT(n)   asm volatile("cp.async.wait_group %0;" :: "n"(n) : "memory")

// 64x128 floats = 2048 float4, 256 thr -> 8 each
__device__ __forceinline__ void cpa_tile(u32 sdst, const float* __restrict__ g, int t) {
#pragma unroll
    for (int i = 0; i < 8; i++)
        CPA16(sdst + (u32)(t + 256 * i) * 16u, g + (size_t)(t + 256 * i) * 4);
}

// ---------------- setup ----------------
__global__ void k_prep(const float* __restrict__ W0, const float* __restrict__ W1,
                       const float* __restrict__ W2, const float* __restrict__ W3,
                       float* __restrict__ Wt) {
    int g = blockIdx.x * 256 + threadIdx.x;
    int m = g >> 14;
    int idx = g & 16383;
    int k = idx >> 7, c = idx & 127;
    const float* W = (m == 0) ? W0 : (m == 1) ? W1 : (m == 2) ? W2 : W3;
    Wt[g] = W[c * H + k];
    if (g < NE) g_cntE[g] = 0;
    if (g < ND) g_cntD[g] = 0;
}

__global__ void k_fill(const int* __restrict__ e_d2e, const int* __restrict__ e_e2d) {
    int e = blockIdx.x * blockDim.x + threadIdx.x;
    if (e >= NEDGE) return;
    {
        int d = e_d2e[NEDGE + e];
        int p = atomicAdd(&g_cntE[d], 1);
        if (p < CAP) g_lstE[d * CAP + p] = e_d2e[e];
    }
    {
        int d = e_e2d[NEDGE + e];
        int p = atomicAdd(&g_cntD[d], 1);
        if (p < CAP) g_lstD[d * CAP + p] = e_e2d[e];
    }
}

// ---------------- mean-gather: warp per (node, batch) ----------------
__global__ void k_agg(const float* __restrict__ SRC, const int* __restrict__ cnt,
                      const int* __restrict__ lst, float* __restrict__ agg,
                      int nNodes, long srcStride) {
    int gw = (blockIdx.x * blockDim.x + threadIdx.x) >> 5;
    if (gw >= nNodes * Bn) return;
    int node = gw % nNodes;
    int b    = gw / nNodes;
    int lane = threadIdx.x & 31;

    int deg = cnt[node];
    int n = deg < CAP ? deg : CAP;
    const int* l = lst + node * CAP;
    float4 a = make_float4(0.f, 0.f, 0.f, 0.f);
    const float* base = SRC + (size_t)b * srcStride;
    for (int j = 0; j < n; ++j) {
        int src = l[j];
        float4 v = reinterpret_cast<const float4*>(base + (size_t)src * H)[lane];
        a.x += v.x; a.y += v.y; a.z += v.z; a.w += v.w;
    }
    float sc = 1.0f / fmaxf((float)deg, 1.0f);
    a.x *= sc; a.y *= sc; a.z *= sc; a.w *= sc;
    reinterpret_cast<float4*>(agg + ((size_t)b * nNodes + node) * H)[lane] = a;
}

// ---------------- GEMM inner: 64-k chunk; thread owns cols [4tc..+4)+[64+4tc..+4)
__device__ __forceinline__ void mm_chunk(const float* __restrict__ Xs,
                                         const float* __restrict__ Wc,
                                         int tr, int tc, int kb, u64 acc[4][4]) {
    const float* xb = Xs + tr * 4 * 128 + kb;
    const float* wb = Wc + 4 * tc;
#pragma unroll 2
    for (int k0 = 0; k0 < 64; k0 += 4) {
        float4 xq[4];
#pragma unroll
        for (int i = 0; i < 4; i++)
            xq[i] = *reinterpret_cast<const float4*>(xb + i * 128 + k0);
#pragma unroll
        for (int kk = 0; kk < 4; kk++) {
            const float* wr = wb + (k0 + kk) * 128;
            ulonglong2 wlo = *reinterpret_cast<const ulonglong2*>(wr);
            ulonglong2 whi = *reinterpret_cast<const ulonglong2*>(wr + 64);
#pragma unroll
            for (int i = 0; i < 4; i++) {
                float xs = (kk == 0) ? xq[i].x : (kk == 1) ? xq[i].y
                         : (kk == 2) ? xq[i].z : xq[i].w;
                u64 xd;
                asm("mov.b64 %0, {%1, %1};" : "=l"(xd) : "f"(xs));
                asm("fma.rn.f32x2 %0, %1, %2, %0;" : "+l"(acc[i][0]) : "l"(wlo.x), "l"(xd));
                asm("fma.rn.f32x2 %0, %1, %2, %0;" : "+l"(acc[i][1]) : "l"(wlo.y), "l"(xd));
                asm("fma.rn.f32x2 %0, %1, %2, %0;" : "+l"(acc[i][2]) : "l"(whi.x), "l"(xd));
                asm("fma.rn.f32x2 %0, %1, %2, %0;" : "+l"(acc[i][3]) : "l"(whi.y), "l"(xd));
            }
        }
    }
}

#define SMEM_BYTES ((64 * 128 * 3) * 4)   // X + 2 W chunks = 96 KB

// ---------------- MODE 0: Y = X @ Wt ----------------
__global__ void __launch_bounds__(256, 2)
k_gemm0(const float* __restrict__ X, const float* __restrict__ Wt,
        float* __restrict__ out) {
    extern __shared__ float smx[];
    float* Xs = smx;
    float* Wc0 = smx + 64 * 128;
    float* Wc1 = smx + 2 * 64 * 128;
    const int t = threadIdx.x;
    const size_t row0 = (size_t)blockIdx.x * 64;

    const u32 sX = cvta_s(Xs), sW0 = cvta_s(Wc0), sW1 = cvta_s(Wc1);
    cpa_tile(sX, X + row0 * H, t);
    cpa_tile(sW0, Wt, t);
    CPA_COMMIT();
    cpa_tile(sW1, Wt + 64 * 128, t);
    CPA_COMMIT();

    const int tc = t & 15, tr = t >> 4;
    u64 acc[4][4];
#pragma unroll
    for (int i = 0; i < 4; i++)
#pragma unroll
        for (int j = 0; j < 4; j++) acc[i][j] = 0ull;

    CPA_WAIT(1);
    __syncthreads();
    mm_chunk(Xs, Wc0, tr, tc, 0, acc);
    CPA_WAIT(0);
    __syncthreads();
    mm_chunk(Xs, Wc1, tr, tc, 64, acc);

#pragma unroll
    for (int i = 0; i < 4; i++) {
        float* orow = out + (row0 + tr * 4 + i) * H + 4 * tc;
        ulonglong2 lo, hi;
        lo.x = acc[i][0]; lo.y = acc[i][1];
        hi.x = acc[i][2]; hi.y = acc[i][3];
        *reinterpret_cast<ulonglong2*>(orow) = lo;
        *reinterpret_cast<ulonglong2*>(orow + 64) = hi;
    }
}

// ---------------- Phase-1 E-side: self-GEMM + fused gather + LN ----------------
__global__ void __launch_bounds__(256, 2)
k_gemmE(const float* __restrict__ X, const float* __restrict__ Wt,
        const float* __restrict__ Y,
        const int* __restrict__ cnt, const int* __restrict__ lst,
        const float* __restrict__ ew,
        const float* __restrict__ bias, const float* __restrict__ gamma,
        const float* __restrict__ beta, float* __restrict__ out) {
    extern __shared__ float smx[];
    float* Xs = smx;
    float* Wc0 = smx + 64 * 128;
    float* Wc1 = smx + 2 * 64 * 128;
    const int t = threadIdx.x;
    const size_t row0 = (size_t)blockIdx.x * 64;
    const int b = (int)(row0 / NE);
    const int e0 = (int)(row0 % NE);

    const u32 sX = cvta_s(Xs), sW0 = cvta_s(Wc0), sW1 = cvta_s(Wc1);
    cpa_tile(sX, X + row0 * H, t);
    cpa_tile(sW0, Wt, t);
    CPA_COMMIT();
    cpa_tile(sW1, Wt + 64 * 128, t);
    CPA_COMMIT();

    const int tc = t & 15, tr = t >> 4;
    u64 acc[4][4];
#pragma unroll
    for (int i = 0; i < 4; i++)
#pragma unroll
        for (int j = 0; j < 4; j++) acc[i][j] = 0ull;

    CPA_WAIT(1);
    __syncthreads();
    mm_chunk(Xs, Wc0, tr, tc, 0, acc);
    CPA_WAIT(0);
    __syncthreads();
    mm_chunk(Xs, Wc1, tr, tc, 64, acc);

    const float4 b_lo = *reinterpret_cast<const float4*>(bias  + 4 * tc);
    const float4 b_hi = *reinterpret_cast<const float4*>(bias  + 64 + 4 * tc);
    const float4 g_lo = *reinterpret_cast<const float4*>(gamma + 4 * tc);
    const float4 g_hi = *reinterpret_cast<const float4*>(gamma + 64 + 4 * tc);
    const float4 z_lo = *reinterpret_cast<const float4*>(beta  + 4 * tc);
    const float4 z_hi = *reinterpret_cast<const float4*>(beta  + 64 + 4 * tc);
    const float* Yb = Y + (size_t)b * ND * H + 4 * tc;

#pragma unroll
    for (int i = 0; i < 4; i++) {
        const int e = e0 + tr * 4 + i;
        const size_t r = row0 + tr * 4 + i;
        int deg = cnt[e];
        int n = deg < CAP ? deg : CAP;
        const int* l = lst + e * CAP;
        float sc = (1.0f / (1.0f + __expf(-ew[e]))) / fmaxf((float)deg, 1.0f);

        float4 agl = make_float4(0.f, 0.f, 0.f, 0.f);
        float4 agh = make_float4(0.f, 0.f, 0.f, 0.f);
        for (int p = 0; p < n; ++p) {
            const float* yr = Yb + (size_t)l[p] * H;
            float4 v = *reinterpret_cast<const float4*>(yr);
            float4 w = *reinterpret_cast<const float4*>(yr + 64);
            agl.x += v.x; agl.y += v.y; agl.z += v.z; agl.w += v.w;
            agh.x += w.x; agh.y += w.y; agh.z += w.z; agh.w += w.w;
        }

        const float* xrow = X + r * H + 4 * tc;
        float4 x_lo = *reinterpret_cast<const float4*>(xrow);
        float4 x_hi = *reinterpret_cast<const float4*>(xrow + 64);

        float tv[8];
        {
            float p0, p1, p2, p3;
            asm("mov.b64 {%0, %1}, %2;" : "=f"(p0), "=f"(p1) : "l"(acc[i][0]));
            asm("mov.b64 {%0, %1}, %2;" : "=f"(p2), "=f"(p3) : "l"(acc[i][1]));
            tv[0] = fmaxf(p0 + agl.x * sc + b_lo.x, 0.f) + x_lo.x;
            tv[1] = fmaxf(p1 + agl.y * sc + b_lo.y, 0.f) + x_lo.y;
            tv[2] = fmaxf(p2 + agl.z * sc + b_lo.z, 0.f) + x_lo.z;
            tv[3] = fmaxf(p3 + agl.w * sc + b_lo.w, 0.f) + x_lo.w;
            asm("mov.b64 {%0, %1}, %2;" : "=f"(p0), "=f"(p1) : "l"(acc[i][2]));
            asm("mov.b64 {%0, %1}, %2;" : "=f"(p2), "=f"(p3) : "l"(acc[i][3]));
            tv[4] = fmaxf(p0 + agh.x * sc + b_hi.x, 0.f) + x_hi.x;
            tv[5] = fmaxf(p1 + agh.y * sc + b_hi.y, 0.f) + x_hi.y;
            tv[6] = fmaxf(p2 + agh.z * sc + b_hi.z, 0.f) + x_hi.z;
            tv[7] = fmaxf(p3 + agh.w * sc + b_hi.w, 0.f) + x_hi.w;
        }
        float ssum = 0.f, q = 0.f;
#pragma unroll
        for (int c = 0; c < 8; c++) { ssum += tv[c]; q += tv[c] * tv[c]; }
#pragma unroll
        for (int o = 8; o; o >>= 1) {
            ssum += __shfl_xor_sync(0xffffffffu, ssum, o, 16);
            q    += __shfl_xor_sync(0xffffffffu, q, o, 16);
        }
        float m = ssum * (1.0f / 128.0f);
        float rstd = rsqrtf(q * (1.0f / 128.0f) - m * m + 1e-5f);

        float* orow = out + r * H + 4 * tc;
        float4 o_lo, o_hi;
        o_lo.x = (tv[0] - m) * rstd * g_lo.x + z_lo.x;
        o_lo.y = (tv[1] - m) * rstd * g_lo.y + z_lo.y;
        o_lo.z = (tv[2] - m) * rstd * g_lo.z + z_lo.z;
        o_lo.w = (tv[3] - m) * rstd * g_lo.w + z_lo.w;
        o_hi.x = (tv[4] - m) * rstd * g_hi.x + z_hi.x;
        o_hi.y = (tv[5] - m) * rstd * g_hi.y + z_hi.y;
        o_hi.z = (tv[6] - m) * rstd * g_hi.z + z_hi.z;
        o_hi.w = (tv[7] - m) * rstd * g_hi.w + z_hi.w;
        *reinterpret_cast<float4*>(orow) = o_lo;
        *reinterpret_cast<float4*>(orow + 64) = o_hi;
    }
}

// ---------------- Phase-2 D-side dual GEMM + LN ----------------
__global__ void __launch_bounds__(256, 2)
k_gemmD(const float* __restrict__ X, const float* __restrict__ W1t,
        const float* __restrict__ A, const float* __restrict__ W2t,
        const float* __restrict__ bias, const float* __restrict__ gamma,
        const float* __restrict__ beta, float* __restrict__ out) {
    extern __shared__ float smx[];
    float* Xs = smx;
    float* Wc0 = smx + 64 * 128;
    float* Wc1 = smx + 2 * 64 * 128;
    const int t = threadIdx.x;
    const size_t row0 = (size_t)blockIdx.x * 64;

    const u32 sX = cvta_s(Xs), sW0 = cvta_s(Wc0), sW1 = cvta_s(Wc1);
    cpa_tile(sX, X + row0 * H, t);
    cpa_tile(sW0, W1t, t);
    CPA_COMMIT();
    cpa_tile(sW1, W1t + 64 * 128, t);
    CPA_COMMIT();

    const int tc = t & 15, tr = t >> 4;
    u64 acc[4][4];
#pragma unroll
    for (int i = 0; i < 4; i++)
#pragma unroll
        for (int j = 0; j < 4; j++) acc[i][j] = 0ull;

    CPA_WAIT(1);
    __syncthreads();
    mm_chunk(Xs, Wc0, tr, tc, 0, acc);
    CPA_WAIT(0);
    __syncthreads();
    cpa_tile(sW0, W2t, t);
    CPA_COMMIT();
    mm_chunk(Xs, Wc1, tr, tc, 64, acc);
    __syncthreads();
    cpa_tile(sX, A + row0 * H, t);
    cpa_tile(sW1, W2t + 64 * 128, t);
    CPA_COMMIT();
    CPA_WAIT(0);
    __syncthreads();
    mm_chunk(Xs, Wc0, tr, tc, 0, acc);
    mm_chunk(Xs, Wc1, tr, tc, 64, acc);

    const float4 b_lo = *reinterpret_cast<const float4*>(bias  + 4 * tc);
    const float4 b_hi = *reinterpret_cast<const float4*>(bias  + 64 + 4 * tc);
    const float4 g_lo = *reinterpret_cast<const float4*>(gamma + 4 * tc);
    const float4 g_hi = *reinterpret_cast<const float4*>(gamma + 64 + 4 * tc);
    const float4 z_lo = *reinterpret_cast<const float4*>(beta  + 4 * tc);
    const float4 z_hi = *reinterpret_cast<const float4*>(beta  + 64 + 4 * tc);

#pragma unroll
    for (int i = 0; i < 4; i++) {
        const size_t r = row0 + tr * 4 + i;
        const float* xrow = X + r * H + 4 * tc;
        float4 x_lo = *reinterpret_cast<const float4*>(xrow);
        float4 x_hi = *reinterpret_cast<const float4*>(xrow + 64);

        float tv[8];
        {
            float p0, p1, p2, p3;
            asm("mov.b64 {%0, %1}, %2;" : "=f"(p0), "=f"(p1) : "l"(acc[i][0]));
            asm("mov.b64 {%0, %1}, %2;" : "=f"(p2), "=f"(p3) : "l"(acc[i][1]));
            tv[0] = fmaxf(p0 + b_lo.x, 0.f) + x_lo.x;
            tv[1] = fmaxf(p1 + b_lo.y, 0.f) + x_lo.y;
            tv[2] = fmaxf(p2 + b_lo.z, 0.f) + x_lo.z;
            tv[3] = fmaxf(p3 + b_lo.w, 0.f) + x_lo.w;
            asm("mov.b64 {%0, %1}, %2;" : "=f"(p0), "=f"(p1) : "l"(acc[i][2]));
            asm("mov.b64 {%0, %1}, %2;" : "=f"(p2), "=f"(p3) : "l"(acc[i][3]));
            tv[4] = fmaxf(p0 + b_hi.x, 0.f) + x_hi.x;
            tv[5] = fmaxf(p1 + b_hi.y, 0.f) + x_hi.y;
            tv[6] = fmaxf(p2 + b_hi.z, 0.f) + x_hi.z;
            tv[7] = fmaxf(p3 + b_hi.w, 0.f) + x_hi.w;
        }
        float ssum = 0.f, q = 0.f;
#pragma unroll
        for (int c = 0; c < 8; c++) { ssum += tv[c]; q += tv[c] * tv[c]; }
#pragma unroll
        for (int o = 8; o; o >>= 1) {
            ssum += __shfl_xor_sync(0xffffffffu, ssum, o, 16);
            q    += __shfl_xor_sync(0xffffffffu, q, o, 16);
        }
        float m = ssum * (1.0f / 128.0f);
        float rstd = rsqrtf(q * (1.0f / 128.0f) - m * m + 1e-5f);

        float* orow = out + r * H + 4 * tc;
        float4 o_lo, o_hi;
        o_lo.x = (tv[0] - m) * rstd * g_lo.x + z_lo.x;
        o_lo.y = (tv[1] - m) * rstd * g_lo.y + z_lo.y;
        o_lo.z = (tv[2] - m) * rstd * g_lo.z + z_lo.z;
        o_lo.w = (tv[3] - m) * rstd * g_lo.w + z_lo.w;
        o_hi.x = (tv[4] - m) * rstd * g_hi.x + z_hi.x;
        o_hi.y = (tv[5] - m) * rstd * g_hi.y + z_hi.y;
        o_hi.z = (tv[6] - m) * rstd * g_hi.z + z_hi.z;
        o_hi.w = (tv[7] - m) * rstd * g_hi.w + z_hi.w;
        *reinterpret_cast<float4*>(orow) = o_lo;
        *reinterpret_cast<float4*>(orow + 64) = o_hi;
    }
}

// ---------------- launch ----------------
extern "C" void kernel_launch(void* const* d_in, const int* in_sizes, int n_in,
                              void* d_out, int out_size) {
    const float* hD    = (const float*)d_in[0];
    const float* hE    = (const float*)d_in[1];
    const int*   e_d2e = (const int*)d_in[2];
    const int*   e_e2d = (const int*)d_in[3];
    const float* ew    = (const float*)d_in[4];
    const float* W_d2e    = (const float*)d_in[5];
    const float* W_e_self = (const float*)d_in[6];
    const float* b_e   = (const float*)d_in[7];
    const float* g_e   = (const float*)d_in[8];
    const float* be_e  = (const float*)d_in[9];
    const float* W_e2d    = (const float*)d_in[10];
    const float* W_d_self = (const float*)d_in[11];
    const float* b_d   = (const float*)d_in[12];
    const float* g_d   = (const float*)d_in[13];
    const float* be_d  = (const float*)d_in[14];

    float* out_hD = (float*)d_out;
    float* out_hE = (float*)d_out + (size_t)Bn * ND * H;

    float *pY, *pAggPre, *pWt;
    int *pCntE, *pLstE, *pCntD, *pLstD;
    cudaGetSymbolAddress((void**)&pY, g_Y);
    cudaGetSymbolAddress((void**)&pAggPre, g_aggPre);
    cudaGetSymbolAddress((void**)&pWt, g_Wt);
    cudaGetSymbolAddress((void**)&pCntE, g_cntE);
    cudaGetSymbolAddress((void**)&pLstE, g_lstE);
    cudaGetSymbolAddress((void**)&pCntD, g_cntD);
    cudaGetSymbolAddress((void**)&pLstD, g_lstD);

    float* Wt_d2e    = pWt + 0 * H * H;
    float* Wt_e_self = pWt + 1 * H * H;
    float* Wt_e2d    = pWt + 2 * H * H;
    float* Wt_d_self = pWt + 3 * H * H;

    cudaFuncSetAttribute(k_gemm0, cudaFuncAttributeMaxDynamicSharedMemorySize, SMEM_BYTES);
    cudaFuncSetAttribute(k_gemmE, cudaFuncAttributeMaxDynamicSharedMemorySize, SMEM_BYTES);
    cudaFuncSetAttribute(k_gemmD, cudaFuncAttributeMaxDynamicSharedMemorySize, SMEM_BYTES);

    // ---- setup ----
    k_prep<<<256, 256>>>(W_d2e, W_e_self, W_e2d, W_d_self, pWt);
    k_fill<<<NEDGE / 256, 256>>>(e_d2e, e_e2d);

    // ---- Phase 1: D -> E ----
    k_gemm0<<<(Bn * ND) / 64, 256, SMEM_BYTES>>>(hD, Wt_d2e, pY);
    k_gemmE<<<(Bn * NE) / 64, 256, SMEM_BYTES>>>(hE, Wt_e_self, pY, pCntE, pLstE, ew,
                                                 b_e, g_e, be_e, out_hE);

    // ---- Phase 2: E -> D (commuted aggregation + dual GEMM) ----
    k_agg<<<(ND * Bn * 32) / 256, 256>>>(out_hE, pCntD, pLstD, pAggPre, ND, (long)NE * H);
    k_gemmD<<<(Bn * ND) / 64, 256, SMEM_BYTES>>>(hD, Wt_d_self, pAggPre, Wt_e2d,
                                                 b_d, g_d, be_d, out_hD);
}